// round 13
// baseline (speedup 1.0000x reference)
#include <cuda_runtime.h>
#include <cuda_bf16.h>
#include <math.h>

#define F 128
#define NMAX 50000
#define EMAX 800000
#define CAP 64      // bucket capacity per destination row (P(deg>=64) ~ 1e-13)

typedef unsigned int       u32;
typedef unsigned short     u16;
typedef unsigned long long u64;

// static scratch (no allocations allowed; zero-initialized at load)
__device__ u16    g_Shi[(size_t)NMAX * F];         // bf16 hi of S
__device__ u16    g_Slo[(size_t)NMAX * F];         // bf16 residual of S
__device__ float2 g_slots[(size_t)NMAX * CAP];     // (src_bits, w) buckets
__device__ int    g_cnt[NMAX];                     // reset by epilogue for next call
__device__ float4 g_over[EMAX];                    // overflow edges
__device__ int    g_overcnt;

// ---------------------------------------------------------------------------
// Kernel 1: bucket fill. FOUR edges per thread: 4 independent atomic->store
// chains (fill is atomic-latency-bound: issue 5.5% @ occ 77%).
// Thread t (< quarter) exclusively owns edges {t, t+q, t+2q, t+3q}.
// ---------------------------------------------------------------------------
__global__ void fill_kernel(const float* __restrict__ edge_w,
                            const int* __restrict__ edge_src,
                            const int* __restrict__ edge_dst,
                            int E, int q) {
    int t = blockIdx.x * blockDim.x + threadIdx.x;
    if (t >= q) return;
    #pragma unroll
    for (int u = 0; u < 4; u++) {
        int e = t + u * q;
        if (e >= E) continue;
        int d = edge_dst[e];
        int s = edge_src[e];
        float w = edge_w[e];
        int pos = atomicAdd(&g_cnt[d], 1);
        if (pos < CAP) {
            g_slots[(size_t)d * CAP + pos] = make_float2(__int_as_float(s), w);
        } else {
            int o = atomicAdd(&g_overcnt, 1);
            if (o < EMAX)
                g_over[o] = make_float4(__int_as_float(s), __int_as_float(d), w, 0.f);
        }
    }
}

// ---------------------------------------------------------------------------
// Kernel 2: gather + S fuse + bf16 hi/lo split. One warp per row (R12-proven).
// ---------------------------------------------------------------------------
__global__ void gather_kernel(const float* __restrict__ x,
                              const float* __restrict__ h0,
                              const float* __restrict__ alpha_p,
                              int Nn) {
    int gtid = blockIdx.x * blockDim.x + threadIdx.x;
    int row = gtid >> 5;
    int lane = gtid & 31;
    if (row >= Nn) return;

    float alpha = alpha_p[0];
    float oma = 1.0f - alpha;

    int cnt_raw = g_cnt[row];
    int cnt = min(cnt_raw, CAP);

    float4 acc = make_float4(0.f, 0.f, 0.f, 0.f);
    const float2* slotp = g_slots + (size_t)row * CAP;

    for (int base = 0; base < cnt; base += 32) {
        int m = min(32, cnt - base);
        float2 myslot = (lane < m) ? slotp[base + lane] : make_float2(0.f, 0.f);
        int ms = __float_as_int(myslot.x);
        #pragma unroll 4
        for (int e = 0; e < m; e++) {
            int   s  = __shfl_sync(0xffffffffu, ms, e);
            float wt = __shfl_sync(0xffffffffu, myslot.y, e);
            float4 v = ((const float4*)(x + (size_t)s * F))[lane];
            acc.x += wt * v.x;
            acc.y += wt * v.y;
            acc.z += wt * v.z;
            acc.w += wt * v.w;
        }
    }

    if (cnt_raw > CAP) {                       // statistically never
        int oc = g_overcnt;
        if (oc > EMAX) oc = EMAX;
        for (int o = 0; o < oc; o++) {
            float4 ov = g_over[o];
            if (__float_as_int(ov.y) == row) {
                int s = __float_as_int(ov.x);
                float wt = ov.z;
                float4 v = ((const float4*)(x + (size_t)s * F))[lane];
                acc.x += wt * v.x;
                acc.y += wt * v.y;
                acc.z += wt * v.z;
                acc.w += wt * v.w;
            }
        }
    }

    float4 hv = ((const float4*)(h0 + (size_t)row * F))[lane];
    float Sx = oma * acc.x + alpha * hv.x;
    float Sy = oma * acc.y + alpha * hv.y;
    float Sz = oma * acc.z + alpha * hv.z;
    float Sw = oma * acc.w + alpha * hv.w;

    __nv_bfloat162 h01 = __floats2bfloat162_rn(Sx, Sy);
    __nv_bfloat162 h23 = __floats2bfloat162_rn(Sz, Sw);
    __nv_bfloat162 l01 = __floats2bfloat162_rn(
        Sx - __bfloat162float(h01.x), Sy - __bfloat162float(h01.y));
    __nv_bfloat162 l23 = __floats2bfloat162_rn(
        Sz - __bfloat162float(h23.x), Sw - __bfloat162float(h23.y));
    u64 hvv = (u64)(*(u32*)&h01) | ((u64)(*(u32*)&h23) << 32);
    u64 lvv = (u64)(*(u32*)&l01) | ((u64)(*(u32*)&l23) << 32);
    *(u64*)&g_Shi[(size_t)row * F + 4 * lane] = hvv;
    *(u64*)&g_Slo[(size_t)row * F + 4 * lane] = lvv;
}

// ---------------------------------------------------------------------------
// Kernel 3: HMMA epilogue with register-prefetch pipeline.
//   out = S @ W' + x; D = Sa@Wa + Sb@Wa + Sa@Wb (fp32 accum).
// R13 vs R12 (epilogue ~33us): next tile's g_Shi/g_Slo LDG.128s issue right
// after this tile's STS+bar, hiding LDG latency behind 48 MMAs + writeout.
// ---------------------------------------------------------------------------
#define SPAD 136                        // u16 row stride (272 bytes)
#define OFF_WTA 0
#define OFF_WTB (128 * SPAD * 2)        // 34816
#define OFF_SA  (2 * 128 * SPAD * 2)    // 69632
#define OFF_SB  (OFF_SA + 16 * SPAD * 2)
#define SMEM_EPI (OFF_SB + 16 * SPAD * 2)   // 78336 bytes

#define MMA_BF16(c, a0, a1, a2, a3, b0, b1) \
    asm volatile("mma.sync.aligned.m16n8k16.row.col.f32.bf16.bf16.f32 " \
        "{%0,%1,%2,%3}, {%4,%5,%6,%7}, {%8,%9}, {%0,%1,%2,%3};" \
        : "+f"((c)[0]), "+f"((c)[1]), "+f"((c)[2]), "+f"((c)[3]) \
        : "r"(a0), "r"(a1), "r"(a2), "r"(a3), "r"(b0), "r"(b1))

#define LDMATRIX_X4(r0, r1, r2, r3, addr) \
    asm volatile("ldmatrix.sync.aligned.m8n8.x4.shared.b16 {%0,%1,%2,%3}, [%4];" \
        : "=r"(r0), "=r"(r1), "=r"(r2), "=r"(r3) : "r"(addr))

__device__ __forceinline__ u32 smem_u32(const void* p) {
    u32 a;
    asm("{ .reg .u64 t; cvta.to.shared.u64 t, %1; cvt.u32.u64 %0, t; }"
        : "=r"(a) : "l"(p));
    return a;
}

__global__ void __launch_bounds__(256, 2)
mma_epilogue_kernel(const float* __restrict__ x,
                    const float* __restrict__ weight,
                    const float* __restrict__ lamda_p,
                    const int* __restrict__ l_p,
                    float* __restrict__ out,
                    int Nn) {
    extern __shared__ char sm[];
    u16* WTa = (u16*)(sm + OFF_WTA);
    u16* WTb = (u16*)(sm + OFF_WTB);
    u16* Sa  = (u16*)(sm + OFF_SA);
    u16* Sb  = (u16*)(sm + OFF_SB);

    int tid  = threadIdx.x;
    int lane = tid & 31;
    int wrp  = tid >> 5;

    // reset counters for the NEXT invocation (off the critical path)
    {
        int gid = blockIdx.x * blockDim.x + tid;
        if (gid < Nn) g_cnt[gid] = 0;
        if (gid == 0) g_overcnt = 0;
    }

    float theta = logf(lamda_p[0] / (float)l_p[0] + 1.0f);
    float omt = 1.0f - theta;

    // Build WT hi/lo: WT[n][k] = W'[k][n] = theta*W[k][n] + (k==n)*(1-theta)
    for (int i = tid; i < F * F; i += 256) {
        int k = i >> 7;
        int n = i & 127;
        float v = theta * weight[i];
        if (k == n) v += omt;
        __nv_bfloat16 h = __float2bfloat16(v);
        float res = v - __bfloat162float(h);
        __nv_bfloat16 l = __float2bfloat16(res);
        WTa[n * SPAD + k] = *(u16*)&h;
        WTb[n * SPAD + k] = *(u16*)&l;
    }
    __syncthreads();

    int m0 = lane >> 2;                // fragment row (0..7)
    int cq = lane & 3;                 // k/n quad (0..3)
    int nt0 = wrp * 2;                 // this warp's two n-tiles

    // ---- hoist B fragments (W' constant across all tiles): 64 u32 regs
    u32 Bf[2][8][4];
    #pragma unroll
    for (int j = 0; j < 2; j++) {
        int n = (nt0 + j) * 8 + m0;
        #pragma unroll
        for (int ks = 0; ks < 8; ks++) {
            int kk = ks * 16 + cq * 2;
            Bf[j][ks][0] = *(u32*)&WTa[n * SPAD + kk];
            Bf[j][ks][1] = *(u32*)&WTa[n * SPAD + kk + 8];
            Bf[j][ks][2] = *(u32*)&WTb[n * SPAD + kk];
            Bf[j][ks][3] = *(u32*)&WTb[n * SPAD + kk + 8];
        }
    }

    // ldmatrix lane addressing: row = lane&15, col-block = (lane>>4)*8
    u32 lm_row = lane & 15;
    u32 lm_col = (lane >> 4) << 3;
    u32 addrSa = smem_u32(Sa) + (lm_row * SPAD + lm_col) * 2;
    u32 addrSb = smem_u32(Sb) + (lm_row * SPAD + lm_col) * 2;

    // staging assignment: thread -> (row r, 8-col segment seg)
    int sr  = tid >> 4;
    int seg = tid & 15;

    int ntiles = (Nn + 15) >> 4;

    // ---- pipeline prologue: load first tile into regs
    uint4 hv = make_uint4(0, 0, 0, 0), lv = make_uint4(0, 0, 0, 0);
    {
        int row = (blockIdx.x << 4) + sr;
        if (blockIdx.x < ntiles && row < Nn) {
            size_t gidx = (size_t)row * F + seg * 8;
            hv = *(const uint4*)&g_Shi[gidx];
            lv = *(const uint4*)&g_Slo[gidx];
        }
    }

    for (int t = blockIdx.x; t < ntiles; t += gridDim.x) {
        int row0 = t << 4;

        // ---- stage current tile from regs
        *(uint4*)&Sa[sr * SPAD + seg * 8] = hv;
        *(uint4*)&Sb[sr * SPAD + seg * 8] = lv;
        __syncthreads();

        // ---- prefetch next tile (LDG latency hides behind MMA below)
        {
            int tn = t + gridDim.x;
            hv = make_uint4(0, 0, 0, 0);
            lv = make_uint4(0, 0, 0, 0);
            int row = (tn << 4) + sr;
            if (tn < ntiles && row < Nn) {
                size_t gidx = (size_t)row * F + seg * 8;
                hv = *(const uint4*)&g_Shi[gidx];
                lv = *(const uint4*)&g_Slo[gidx];
            }
        }

        // ---- mainloop: 8 k-steps x (ldmatrix A hi/lo + 6 mma)
        float acc0[4] = {0.f, 0.f, 0.f, 0.f};
        float acc1[4] = {0.f, 0.f, 0.f, 0.f};

        #pragma unroll
        for (int ks = 0; ks < 8; ks++) {
            u32 ah0, ah1, ah2, ah3, al0, al1, al2, al3;
            LDMATRIX_X4(ah0, ah1, ah2, ah3, addrSa + ks * 32);
            LDMATRIX_X4(al0, al1, al2, al3, addrSb + ks * 32);

            MMA_BF16(acc0, ah0, ah1, ah2, ah3, Bf[0][ks][0], Bf[0][ks][1]);
            MMA_BF16(acc0, al0, al1, al2, al3, Bf[0][ks][0], Bf[0][ks][1]);
            MMA_BF16(acc0, ah0, ah1, ah2, ah3, Bf[0][ks][2], Bf[0][ks][3]);

            MMA_BF16(acc1, ah0, ah1, ah2, ah3, Bf[1][ks][0], Bf[1][ks][1]);
            MMA_BF16(acc1, al0, al1, al2, al3, Bf[1][ks][0], Bf[1][ks][1]);
            MMA_BF16(acc1, ah0, ah1, ah2, ah3, Bf[1][ks][2], Bf[1][ks][3]);
        }

        // ---- writeout: D + x residual
        int r0 = row0 + m0;
        int r1 = row0 + m0 + 8;
        #pragma unroll
        for (int j = 0; j < 2; j++) {
            float* ac = j ? acc1 : acc0;
            int col = (nt0 + j) * 8 + cq * 2;
            if (r0 < Nn) {
                float2 xv = *(const float2*)&x[(size_t)r0 * F + col];
                float2 o = make_float2(ac[0] + xv.x, ac[1] + xv.y);
                *(float2*)&out[(size_t)r0 * F + col] = o;
            }
            if (r1 < Nn) {
                float2 xv = *(const float2*)&x[(size_t)r1 * F + col];
                float2 o = make_float2(ac[2] + xv.x, ac[3] + xv.y);
                *(float2*)&out[(size_t)r1 * F + col] = o;
            }
        }
        __syncthreads();   // protect S staging before next iteration's store
    }
}

// ---------------------------------------------------------------------------
extern "C" void kernel_launch(void* const* d_in, const int* in_sizes, int n_in,
                              void* d_out, int out_size) {
    const float* x      = (const float*)d_in[0];
    const float* h0     = (const float*)d_in[1];
    const float* ew     = (const float*)d_in[2];
    const float* weight = (const float*)d_in[3];
    const float* lamda  = (const float*)d_in[4];
    const float* alpha  = (const float*)d_in[5];
    const int*   esrc   = (const int*)d_in[6];
    const int*   edst   = (const int*)d_in[7];
    const int*   lp     = (const int*)d_in[8];

    int Nn = in_sizes[0] / F;
    int E  = in_sizes[2];
    float* out = (float*)d_out;

    // 1) bucket fill, 4 edges per thread (exclusive: t < q)
    int q = (E + 3) / 4;
    fill_kernel<<<(q + 255) / 256, 256>>>(ew, esrc, edst, E, q);

    // 2) gather + S fuse + bf16 split (one warp per row)
    long long gthreads = (long long)Nn * 32;
    gather_kernel<<<(int)((gthreads + 255) / 256), 256>>>(x, h0, alpha, Nn);

    // 3) HMMA epilogue with register-prefetch pipeline
    cudaFuncSetAttribute(mma_epilogue_kernel,
                         cudaFuncAttributeMaxDynamicSharedMemorySize, SMEM_EPI);
    mma_epilogue_kernel<<<296, 256, SMEM_EPI>>>(x, weight, lamda, lp, out, Nn);
}